// round 2
// baseline (speedup 1.0000x reference)
#include <cuda_runtime.h>

// DynamicGraphModule_15144054686343
//
// Reference math reduces analytically:
//   scores[i,j] = row_term[i] + col_term[j] + b   (rank-1 + const)
//   adj = where(corr > 1.5, corr, 0)   -> elements in {0} U (1.5, inf)
//   adj = where(adj < -1.5, adj, 0)    -> identically ZERO
//   out = adj @ (e @ W_gcn) + b_gcn    == broadcast(b_gcn) exactly
//
// Kernel: broadcast b_gcn [512] into out [1, 4096, 512] (8 MB of fp32 stores).
//
// R1 tuning: one bias LDG per thread held in register, then 8 independent
// STG.128 per thread. 256 blocks x 256 threads = 65536 threads, 8 stores each
// = 524288 float4 stores. Mapping:
//   tid in block: col4 = tid & 127 (float4 column), rsub = tid >> 7 (0/1)
//   block b owns rows [b*16, b*16+16), thread writes rows b*16 + rsub + 2*i.

static constexpr int N_ROWS     = 4096;
static constexpr int D_OUT_VEC4 = 128;   // 512 floats per row = 128 float4
static constexpr int ROWS_PER_BLK = 16;  // 4096 / 256 blocks
static constexpr int STORES_PER_THREAD = 8;

__global__ void __launch_bounds__(256)
broadcast_bias_kernel(const float4* __restrict__ bias4,
                      float4* __restrict__ out4)
{
    const int tid  = threadIdx.x;
    const int col4 = tid & (D_OUT_VEC4 - 1);   // 0..127
    const int rsub = tid >> 7;                 // 0 or 1
    const int row0 = blockIdx.x * ROWS_PER_BLK + rsub;

    const float4 b = bias4[col4];              // one load, L1-broadcast across warps

    float4* p = out4 + (size_t)row0 * D_OUT_VEC4 + col4;
    const size_t stride = 2 * D_OUT_VEC4;      // 2 rows of float4

#pragma unroll
    for (int i = 0; i < STORES_PER_THREAD; ++i) {
        p[i * stride] = b;                     // 8 independent STG.128
    }
}

extern "C" void kernel_launch(void* const* d_in, const int* in_sizes, int n_in,
                              void* d_out, int out_size)
{
    // metadata order:
    // 0 spans_embeddings, 1 W_c1, 2 b_c1, 3 W_c2, 4 b_c2,
    // 5 W_link, 6 b_link, 7 W_gcn, 8 b_gcn
    const float4* bias4 = (const float4*)d_in[8];
    float4* out4 = (float4*)d_out;

    // out_size = 4096 * 512 exactly; fixed mapping covers it fully.
    (void)in_sizes; (void)n_in; (void)out_size;

    broadcast_bias_kernel<<<N_ROWS / ROWS_PER_BLK, 256>>>(bias4, out4);
}

// round 3
// speedup vs baseline: 1.0048x; 1.0048x over previous
#include <cuda_runtime.h>

// DynamicGraphModule_15144054686343
//
// Reference math reduces analytically:
//   scores[i,j] = row_term[i] + col_term[j] + b   (rank-1 + const)
//   adj = where(corr > 1.5, corr, 0)   -> elements in {0} U (1.5, inf)
//   adj = where(adj < -1.5, adj, 0)    -> identically ZERO
//   out = adj @ (e @ W_gcn) + b_gcn    == broadcast(b_gcn) exactly
//
// Kernel: broadcast b_gcn [512] into out [1, 4096, 512] (8 MB fp32 stores).
//
// R2: duration is pinned to the fixed launch/ramp/drain floor (bench dur was
// bit-identical across 2048-block and 256-block shapes; nothing saturated).
// Shape chosen to minimize tail: 1024 blocks x 256 threads, 2 independent
// STG.128 per thread into the two output halves -> dense uniform store stream,
// single wave ramp, earliest possible last-store.

static constexpr int D_OUT_VEC4 = 128;          // 512 floats per row = 128 float4
static constexpr int TOTAL_VEC4 = 4096 * 128;   // 524288 float4 total
static constexpr int HALF_VEC4  = TOTAL_VEC4 / 2;

__global__ void __launch_bounds__(256)
broadcast_bias_kernel(const float4* __restrict__ bias4,
                      float4* __restrict__ out4)
{
    const int idx  = blockIdx.x * blockDim.x + threadIdx.x;  // 0..262143
    const float4 b = bias4[idx & (D_OUT_VEC4 - 1)];          // one L1/L2-broadcast load

    // Two independent, fully coalesced 128-bit stores (same column phase in
    // both halves since HALF_VEC4 is a multiple of 128).
    out4[idx]             = b;
    out4[idx + HALF_VEC4] = b;
}

extern "C" void kernel_launch(void* const* d_in, const int* in_sizes, int n_in,
                              void* d_out, int out_size)
{
    // metadata order:
    // 0 spans_embeddings, 1 W_c1, 2 b_c1, 3 W_c2, 4 b_c2,
    // 5 W_link, 6 b_link, 7 W_gcn, 8 b_gcn
    const float4* bias4 = (const float4*)d_in[8];
    float4* out4 = (float4*)d_out;
    (void)in_sizes; (void)n_in; (void)out_size;   // out_size = 4096*512 exactly

    broadcast_bias_kernel<<<HALF_VEC4 / 256, 256>>>(bias4, out4);
}